// round 2
// baseline (speedup 1.0000x reference)
#include <cuda_runtime.h>

// Problem constants
#define H_ 128
#define W_ 128
#define C_ 32
#define BS_ 8
#define NKP_ 11                      // num_kp + 1
#define NPIX_ (BS_ * NKP_ * H_ * W_) // 1,441,792 pixels (divisible by 32)
#define PIX_PER_BLOCK_ 32
#define NBLOCKS_ (NPIX_ / PIX_PER_BLOCK_)   // 45056

__global__ void __launch_bounds__(256) deform_kernel(
    const float* __restrict__ src,   // (H, W, C)
    const float* __restrict__ mot,   // (NPIX, 2)
    float* __restrict__ out)         // (NPIX, C)
{
    __shared__ float4 s_w[PIX_PER_BLOCK_];   // corner weights (nw, ne, sw, se)
    __shared__ int4   s_o[PIX_PER_BLOCK_];   // clamped float4-base offsets per corner

    const int t = threadIdx.x;
    const int blockPix = blockIdx.x * PIX_PER_BLOCK_;

    // ---- Phase 1: warp 0 computes per-pixel weights + offsets for 32 pixels ----
    if (t < PIX_PER_BLOCK_) {
        const int pix = blockPix + t;
        float2 g = __ldg(((const float2*)mot) + pix);
        float gx = fmaf(g.x, (float)(W_ / 2), (float)(W_ / 2) - 0.5f);
        float gy = fmaf(g.y, (float)(H_ / 2), (float)(H_ / 2) - 0.5f);

        float xwf = floorf(gx);
        float ynf = floorf(gy);
        float fx = gx - xwf;     // 'w'
        float fy = gy - ynf;     // 'n'
        float ex = 1.0f - fx;    // 'e'
        float sy = 1.0f - fy;    // 's'

        int x0 = (int)xwf;
        int y0 = (int)ynf;
        int x1 = x0 + 1;
        int y1 = y0 + 1;

        bool mx0 = (x0 >= 0) & (x0 < W_);
        bool mx1 = (x1 >= 0) & (x1 < W_);
        bool my0 = (y0 >= 0) & (y0 < H_);
        bool my1 = (y1 >= 0) & (y1 < H_);

        float4 w;
        w.x = sy * ex * (float)(my0 & mx0);  // nw
        w.y = sy * fx * (float)(my0 & mx1);  // ne
        w.z = fy * ex * (float)(my1 & mx0);  // sw
        w.w = fy * fx * (float)(my1 & mx1);  // se

        int xc0 = mx0 ? x0 : 0;
        int xc1 = mx1 ? x1 : 0;
        int yc0 = my0 ? y0 : 0;
        int yc1 = my1 ? y1 : 0;

        int4 o;
        o.x = (yc0 * W_ + xc0) << 3;   // float4 index of (y0,x0,cg=0)
        o.y = (yc0 * W_ + xc1) << 3;
        o.z = (yc1 * W_ + xc0) << 3;
        o.w = (yc1 * W_ + xc1) << 3;

        s_w[t] = w;
        s_o[t] = o;
    }
    __syncthreads();

    // ---- Phase 2: all 256 threads: pure data movement + FMA ----
    const int pl = t >> 3;       // local pixel 0..31
    const int cg = t & 7;        // channel group (float4)

    float4 w = s_w[pl];
    int4   o = s_o[pl];

    const float4* s4 = (const float4*)src;
    float4 v00 = __ldg(s4 + o.x + cg);
    float4 v01 = __ldg(s4 + o.y + cg);
    float4 v10 = __ldg(s4 + o.z + cg);
    float4 v11 = __ldg(s4 + o.w + cg);

    float4 acc;
    acc.x = fmaf(w.x, v00.x, fmaf(w.y, v01.x, fmaf(w.z, v10.x, w.w * v11.x)));
    acc.y = fmaf(w.x, v00.y, fmaf(w.y, v01.y, fmaf(w.z, v10.y, w.w * v11.y)));
    acc.z = fmaf(w.x, v00.z, fmaf(w.y, v01.z, fmaf(w.z, v10.z, w.w * v11.z)));
    acc.w = fmaf(w.x, v00.w, fmaf(w.y, v01.w, fmaf(w.z, v10.w, w.w * v11.w)));

    ((float4*)out)[((blockPix + pl) << 3) + cg] = acc;
}

extern "C" void kernel_launch(void* const* d_in, const int* in_sizes, int n_in,
                              void* d_out, int out_size)
{
    const float* src = (const float*)d_in[0];   // source (1,H,W,C)
    const float* mot = (const float*)d_in[1];   // motions (BS,NKP,H,W,2)
    float* out = (float*)d_out;

    deform_kernel<<<NBLOCKS_, 256>>>(src, mot, out);
}